// round 17
// baseline (speedup 1.0000x reference)
#include <cuda_runtime.h>
#include <cuda_bf16.h>
#include <cstdint>
#include <math.h>

// ---------------------------------------------------------------------------
// NeuralODE Tsit5 — persistent-CTA kernel, round 16: bf16x3, (32,32) warp tiles.
// R15 (9.67ms) was L1-wavefront bound at wf/mma = 2.0 with (16,32) tiles.
// This round: 8 warps x (M=32, n=32) -> wf/mma = 1.33 (A frags reused by the
// warp's 2 m-tiles; W frags reused across 2 m-tiles). 256 threads, in-place
// activation buffer (sync-separated), SMEM ~104KB.
// ---------------------------------------------------------------------------

#define BATCH   4096
#define DIM     64
#define WIDTH   256
#define NTT     101
#define TM      32
#define NCTA    128
#define THREADS 256

#define AST2 264                // act stride in bf16 elems (528B row)
#define ZB2  72                 // z hi/lo stride in bf16 elems
#define ZST  68                 // y/k fp32 stride

#define ACT_E (TM * AST2)       // 8448 bf16
#define ZB_E  (TM * ZB2)        // 2304 bf16
#define ZK_F  (TM * ZST)        // 2176 floats

// smem: act hi/lo (bf16) + z hi/lo (bf16) + y + 6k (fp32)
#define SMEM_BYTES ((2*ACT_E + 2*ZB_E) * 2 + 7 * ZK_F * 4)   // 103936

// packed pre-split weights, B-fragment order (m16n8k16), uint4 per (tile,lane):
//   {b0_hi, b1_hi, b0_lo, b1_lo}; tile = kt*NT + nt
#define BPK_L0 0                 // KT=4,  NT=32
#define BPK_L1 4096              // KT=16, NT=32
#define BPK_L2 20480
#define BPK_L3 36864             // KT=16, NT=8
#define BPK_TOTAL 40960
__device__ uint4 g_Bpk[BPK_TOTAL];

// Tsit5 tableau
__constant__ float c_A[6][5] = {
    {0.f, 0.f, 0.f, 0.f, 0.f},
    {0.161f, 0.f, 0.f, 0.f, 0.f},
    {-0.008480655492356989f, 0.335480655492357f, 0.f, 0.f, 0.f},
    {2.8971530571054935f, -6.359448489975075f, 4.3622954328695815f, 0.f, 0.f},
    {5.325864828439257f, -11.748883564062828f, 7.4955393428898365f, -0.09249506636175525f, 0.f},
    {5.86145544294642f, -12.92096931784711f, 8.159367898576159f, -0.071584973281401f, -0.028269050394068383f}
};
__constant__ float c_B[6] = {
    0.09646076681806523f, 0.01f, 0.4798896504144996f,
    1.379008574103742f, -3.290069515436081f, 2.324710524099774f
};

// ---- bf16 helpers ----
__device__ __forceinline__ void split_bf(float x, __nv_bfloat16 &h, __nv_bfloat16 &l) {
    h = __float2bfloat16(x);
    l = __float2bfloat16(x - __bfloat162float(h));
}
__device__ __forceinline__ unsigned bfpair(__nv_bfloat16 a, __nv_bfloat16 b) {
    return (unsigned)__bfloat16_as_ushort(a) | ((unsigned)__bfloat16_as_ushort(b) << 16);
}

// mma.sync m16n8k16 bf16
__device__ __forceinline__ void mma16(float *c, unsigned a0, unsigned a1,
                                      unsigned a2, unsigned a3,
                                      unsigned b0, unsigned b1) {
    asm("mma.sync.aligned.m16n8k16.row.col.f32.bf16.bf16.f32 "
        "{%0,%1,%2,%3},{%4,%5,%6,%7},{%8,%9},{%0,%1,%2,%3};"
        : "+f"(c[0]), "+f"(c[1]), "+f"(c[2]), "+f"(c[3])
        : "r"(a0), "r"(a1), "r"(a2), "r"(a3), "r"(b0), "r"(b1));
}

// ---------------------------------------------------------------------------
// Prologue: split W into bf16 hi/lo, pack in m16n8k16 B-fragment order.
// ---------------------------------------------------------------------------
__global__ void pack_kernel(const float *__restrict__ W0, const float *__restrict__ W1,
                            const float *__restrict__ W2, const float *__restrict__ W3) {
    int e = blockIdx.x * blockDim.x + threadIdx.x;
    if (e >= BPK_TOTAL) return;
    const float *W;
    int base, N, NT;
    if (e < BPK_L1)      { W = W0; base = BPK_L0; N = 256; NT = 32; }
    else if (e < BPK_L2) { W = W1; base = BPK_L1; N = 256; NT = 32; }
    else if (e < BPK_L3) { W = W2; base = BPK_L2; N = 256; NT = 32; }
    else                 { W = W3; base = BPK_L3; N = 64;  NT = 8;  }
    int r = e - base;
    int tile = r >> 5, lane = r & 31;
    int kt = tile / NT, nt = tile % NT;
    int t = lane & 3, g = lane >> 2;
    int n  = nt * 8 + g;
    int k0 = kt * 16 + 2 * t;

    float w00 = W[(size_t)(k0    ) * N + n];
    float w01 = W[(size_t)(k0 + 1) * N + n];
    float w10 = W[(size_t)(k0 + 8) * N + n];
    float w11 = W[(size_t)(k0 + 9) * N + n];

    __nv_bfloat16 h00, l00, h01, l01, h10, l10, h11, l11;
    split_bf(w00, h00, l00);
    split_bf(w01, h01, l01);
    split_bf(w10, h10, l10);
    split_bf(w11, h11, l11);

    g_Bpk[e] = make_uint4(bfpair(h00, h01), bfpair(h10, h11),
                          bfpair(l00, l01), bfpair(l10, l11));
}

// ---------------------------------------------------------------------------
// Layer N=256, warp tile (M=32, n=32). 8 warps cover N=256.
// In-place safe: sync after k-loop (all reads done), then epilogue, then sync.
// ---------------------------------------------------------------------------
template <int K, bool ACT>
__device__ __forceinline__ void layer256(const __nv_bfloat16 *inH, const __nv_bfloat16 *inL,
                                         int inst,
                                         __nv_bfloat16 *outH, __nv_bfloat16 *outL,
                                         const uint4 *Bp0, const float *__restrict__ bias) {
    constexpr int KT = K / 16;
    const int tid  = threadIdx.x;
    const int w    = tid >> 5;
    const int lane = tid & 31;
    const int t    = lane & 3, g = lane >> 2;

    const __nv_bfloat16 *pH = inH + g * inst + 2 * t;
    const __nv_bfloat16 *pL = inL + g * inst + 2 * t;
    const int r8 = 8 * inst, r16 = 16 * inst, r24 = 24 * inst;
    const uint4 *Bp = Bp0 + w * 128 + lane;   // w*4 n-tiles * 32 lanes

    float C[2][4][4];
#pragma unroll
    for (int m = 0; m < 2; m++)
#pragma unroll
        for (int j = 0; j < 4; j++)
            C[m][j][0] = C[m][j][1] = C[m][j][2] = C[m][j][3] = 0.f;

#pragma unroll 2
    for (int kt = 0; kt < KT; ++kt) {
        const int kc = kt * 16;
        // m-tile 0 (rows g, g+8)
        unsigned aH0 = *reinterpret_cast<const unsigned *>(pH + kc);
        unsigned aH1 = *reinterpret_cast<const unsigned *>(pH + kc + r8);
        unsigned aH2 = *reinterpret_cast<const unsigned *>(pH + kc + 8);
        unsigned aH3 = *reinterpret_cast<const unsigned *>(pH + kc + r8 + 8);
        unsigned aL0 = *reinterpret_cast<const unsigned *>(pL + kc);
        unsigned aL1 = *reinterpret_cast<const unsigned *>(pL + kc + r8);
        unsigned aL2 = *reinterpret_cast<const unsigned *>(pL + kc + 8);
        unsigned aL3 = *reinterpret_cast<const unsigned *>(pL + kc + r8 + 8);
        // m-tile 1 (rows 16+g, 24+g)
        unsigned bH0 = *reinterpret_cast<const unsigned *>(pH + kc + r16);
        unsigned bH1 = *reinterpret_cast<const unsigned *>(pH + kc + r24);
        unsigned bH2 = *reinterpret_cast<const unsigned *>(pH + kc + r16 + 8);
        unsigned bH3 = *reinterpret_cast<const unsigned *>(pH + kc + r24 + 8);
        unsigned bL0 = *reinterpret_cast<const unsigned *>(pL + kc + r16);
        unsigned bL1 = *reinterpret_cast<const unsigned *>(pL + kc + r24);
        unsigned bL2 = *reinterpret_cast<const unsigned *>(pL + kc + r16 + 8);
        unsigned bL3 = *reinterpret_cast<const unsigned *>(pL + kc + r24 + 8);

#pragma unroll
        for (int j = 0; j < 4; j++) {
            uint4 b = __ldg(Bp + kt * 1024 + j * 32);
            mma16(C[0][j], aH0, aH1, aH2, aH3, b.x, b.y);
            mma16(C[0][j], aL0, aL1, aL2, aL3, b.x, b.y);
            mma16(C[0][j], aH0, aH1, aH2, aH3, b.z, b.w);
            mma16(C[1][j], bH0, bH1, bH2, bH3, b.x, b.y);
            mma16(C[1][j], bL0, bL1, bL2, bL3, b.x, b.y);
            mma16(C[1][j], bH0, bH1, bH2, bH3, b.z, b.w);
        }
    }
    __syncthreads();   // all k-loop reads complete before (possibly in-place) writes

#pragma unroll
    for (int m = 0; m < 2; m++) {
        const int row0 = m * 16 + g;
#pragma unroll
        for (int j = 0; j < 4; j++) {
            const int col = w * 32 + j * 8 + 2 * t;
            float2 bv = *reinterpret_cast<const float2 *>(bias + col);
            float x0 = C[m][j][0] + bv.x, x1 = C[m][j][1] + bv.y;
            float x2 = C[m][j][2] + bv.x, x3 = C[m][j][3] + bv.y;
            if (ACT) { x0 = tanhf(x0); x1 = tanhf(x1); x2 = tanhf(x2); x3 = tanhf(x3); }
            __nv_bfloat16 h0, l0, h1, l1, h2, l2, h3, l3;
            split_bf(x0, h0, l0); split_bf(x1, h1, l1);
            split_bf(x2, h2, l2); split_bf(x3, h3, l3);
            *reinterpret_cast<unsigned *>(outH + row0 * AST2 + col)       = bfpair(h0, h1);
            *reinterpret_cast<unsigned *>(outL + row0 * AST2 + col)       = bfpair(l0, l1);
            *reinterpret_cast<unsigned *>(outH + (row0 + 8) * AST2 + col) = bfpair(h2, h3);
            *reinterpret_cast<unsigned *>(outL + (row0 + 8) * AST2 + col) = bfpair(l2, l3);
        }
    }
    __syncthreads();
}

// ---------------------------------------------------------------------------
// Layer N=64 (K=256): warp tile (M=32, n=8); 8 warps cover N=64. fp32 out.
// ---------------------------------------------------------------------------
__device__ __forceinline__ void layer64(const __nv_bfloat16 *inH, const __nv_bfloat16 *inL,
                                        float *kout,
                                        const uint4 *Bp0, const float *__restrict__ bias) {
    const int tid  = threadIdx.x;
    const int w    = tid >> 5;
    const int lane = tid & 31;
    const int t    = lane & 3, g = lane >> 2;

    const __nv_bfloat16 *pH = inH + g * AST2 + 2 * t;
    const __nv_bfloat16 *pL = inL + g * AST2 + 2 * t;
    const int r8 = 8 * AST2, r16 = 16 * AST2, r24 = 24 * AST2;
    const uint4 *Bp = Bp0 + w * 32 + lane;

    float C[2][4];
#pragma unroll
    for (int m = 0; m < 2; m++)
        C[m][0] = C[m][1] = C[m][2] = C[m][3] = 0.f;

#pragma unroll 4
    for (int kt = 0; kt < 16; ++kt) {
        const int kc = kt * 16;
        unsigned aH0 = *reinterpret_cast<const unsigned *>(pH + kc);
        unsigned aH1 = *reinterpret_cast<const unsigned *>(pH + kc + r8);
        unsigned aH2 = *reinterpret_cast<const unsigned *>(pH + kc + 8);
        unsigned aH3 = *reinterpret_cast<const unsigned *>(pH + kc + r8 + 8);
        unsigned aL0 = *reinterpret_cast<const unsigned *>(pL + kc);
        unsigned aL1 = *reinterpret_cast<const unsigned *>(pL + kc + r8);
        unsigned aL2 = *reinterpret_cast<const unsigned *>(pL + kc + 8);
        unsigned aL3 = *reinterpret_cast<const unsigned *>(pL + kc + r8 + 8);
        unsigned bH0 = *reinterpret_cast<const unsigned *>(pH + kc + r16);
        unsigned bH1 = *reinterpret_cast<const unsigned *>(pH + kc + r24);
        unsigned bH2 = *reinterpret_cast<const unsigned *>(pH + kc + r16 + 8);
        unsigned bH3 = *reinterpret_cast<const unsigned *>(pH + kc + r24 + 8);
        unsigned bL0 = *reinterpret_cast<const unsigned *>(pL + kc + r16);
        unsigned bL1 = *reinterpret_cast<const unsigned *>(pL + kc + r24);
        unsigned bL2 = *reinterpret_cast<const unsigned *>(pL + kc + r16 + 8);
        unsigned bL3 = *reinterpret_cast<const unsigned *>(pL + kc + r24 + 8);

        uint4 b = __ldg(Bp + kt * 256);
        mma16(C[0], aH0, aH1, aH2, aH3, b.x, b.y);
        mma16(C[0], aL0, aL1, aL2, aL3, b.x, b.y);
        mma16(C[0], aH0, aH1, aH2, aH3, b.z, b.w);
        mma16(C[1], bH0, bH1, bH2, bH3, b.x, b.y);
        mma16(C[1], bL0, bL1, bL2, bL3, b.x, b.y);
        mma16(C[1], bH0, bH1, bH2, bH3, b.z, b.w);
    }

    const int col = w * 8 + 2 * t;
    float2 bv = *reinterpret_cast<const float2 *>(bias + col);
#pragma unroll
    for (int m = 0; m < 2; m++) {
        const int row0 = m * 16 + g;
        *reinterpret_cast<float2 *>(kout + row0 * ZST + col) =
            make_float2(C[m][0] + bv.x, C[m][1] + bv.y);
        *reinterpret_cast<float2 *>(kout + (row0 + 8) * ZST + col) =
            make_float2(C[m][2] + bv.x, C[m][3] + bv.y);
    }
    __syncthreads();
}

// ---------------------------------------------------------------------------
__global__ void __launch_bounds__(THREADS, 1)
node_kernel(const float *__restrict__ ts, const float *__restrict__ y0,
            const float *__restrict__ b0, const float *__restrict__ b1,
            const float *__restrict__ b2, const float *__restrict__ b3,
            float *__restrict__ out) {
    extern __shared__ char smc[];
    __nv_bfloat16 *actH = reinterpret_cast<__nv_bfloat16 *>(smc);
    __nv_bfloat16 *actL = actH + ACT_E;
    __nv_bfloat16 *zH   = actL + ACT_E;
    __nv_bfloat16 *zL   = zH + ZB_E;
    float *ybuf = reinterpret_cast<float *>(zL + ZB_E);
    float *kbuf = ybuf + ZK_F;       // 6 * ZK_F

    const int tid = threadIdx.x;
    const int cta = blockIdx.x;

    const uint4 *BpL0 = g_Bpk + BPK_L0;
    const uint4 *BpL1 = g_Bpk + BPK_L1;
    const uint4 *BpL2 = g_Bpk + BPK_L2;
    const uint4 *BpL3 = g_Bpk + BPK_L3;

    // ingest y0 (row-major) -> ybuf (fp32, stride ZST); emit out[0]
    {
        const float *y0c = y0 + (size_t)cta * TM * DIM;
        float *o0 = out + (size_t)cta * TM * DIM;
        for (int i = tid; i < TM * DIM; i += THREADS) {
            const int r = i >> 6, d = i & 63;
            float v = __ldg(y0c + i);
            ybuf[r * ZST + d] = v;
            o0[i] = v;
        }
    }
    __syncthreads();

    for (int tt = 1; tt < NTT; ++tt) {
        const float h = __ldg(ts + tt) - __ldg(ts + tt - 1);

        for (int s = 0; s < 6; ++s) {
            // z = y + h*sum_{j<s} A[s][j]*k_j, split into bf16 hi/lo
            for (int i = tid; i < TM * DIM; i += THREADS) {
                const int r = i >> 6, d = i & 63;
                float v = ybuf[r * ZST + d];
                for (int j = 0; j < s; j++)
                    v += (h * c_A[s][j]) * kbuf[j * ZK_F + r * ZST + d];
                __nv_bfloat16 hv, lv;
                split_bf(v, hv, lv);
                zH[r * ZB2 + d] = hv;
                zL[r * ZB2 + d] = lv;
            }
            __syncthreads();

            layer256<DIM,   true>(zH,   zL,   ZB2,  actH, actL, BpL0, b0);
            layer256<WIDTH, true>(actH, actL, AST2, actH, actL, BpL1, b1);
            layer256<WIDTH, true>(actH, actL, AST2, actH, actL, BpL2, b2);
            layer64(actH, actL, kbuf + s * ZK_F, BpL3, b3);
        }

        // y += h*sum_j B[j]*k_j ; write out[tt] (coalesced)
        {
            float *outc = out + (size_t)tt * (BATCH * DIM) + (size_t)cta * TM * DIM;
            for (int i = tid; i < TM * DIM; i += THREADS) {
                const int r = i >> 6, d = i & 63;
                const int idx = r * ZST + d;
                float v = ybuf[idx];
#pragma unroll
                for (int j = 0; j < 6; j++)
                    v += (h * c_B[j]) * kbuf[j * ZK_F + idx];
                ybuf[idx] = v;
                outc[i] = v;
            }
        }
        __syncthreads();
    }
}

// ---------------------------------------------------------------------------
extern "C" void kernel_launch(void *const *d_in, const int *in_sizes, int n_in,
                              void *d_out, int out_size) {
    const float *ts = (const float *)d_in[0];
    const float *y0 = (const float *)d_in[1];
    const float *W0 = (const float *)d_in[2];
    const float *b0 = (const float *)d_in[3];
    const float *W1 = (const float *)d_in[4];
    const float *b1 = (const float *)d_in[5];
    const float *W2 = (const float *)d_in[6];
    const float *b2 = (const float *)d_in[7];
    const float *W3 = (const float *)d_in[8];
    const float *b3 = (const float *)d_in[9];
    float *out = (float *)d_out;

    pack_kernel<<<(BPK_TOTAL + 255) / 256, 256>>>(W0, W1, W2, W3);

    cudaFuncSetAttribute(node_kernel,
                         cudaFuncAttributeMaxDynamicSharedMemorySize, SMEM_BYTES);
    node_kernel<<<NCTA, THREADS, SMEM_BYTES>>>(ts, y0, b0, b1, b2, b3, out);
}